// round 1
// baseline (speedup 1.0000x reference)
#include <cuda_runtime.h>
#include <cstdint>

#define NHEAD 4
#define DK 64
#define DM 256
#define NN 128
#define MAXB 2048

// Scratch (static __device__ arrays per allocation rules)
__device__ float g_qW[MAXB * NHEAD * DM];   // (q_h @ W_k,h) / TEMP   [b][h][j]
__device__ float g_ctx[MAXB * NHEAD * DM];  // attn @ seq             [b][h][j]

extern __shared__ float s_dyn[];

// ---------------------------------------------------------------------------
// K1: q = src @ w_qs^T ; qW[h] = q_h @ W_k,h  (scaled by 1/TEMP = 0.125)
// 16 batches per CTA, 256 threads. Weight tiles staged transposed in smem.
// ---------------------------------------------------------------------------
#define K1_NB 16
__global__ void __launch_bounds__(256) k1_qw(const float* __restrict__ src,
                                             const float* __restrict__ w_qs,
                                             const float* __restrict__ w_ks,
                                             int B)
{
    float* src_s = s_dyn;            // 16*256
    float* q_s   = s_dyn + 4096;     // 16*256
    float* wt    = s_dyn + 8192;     // 64*257
    int t  = threadIdx.x;
    int b0 = blockIdx.x * K1_NB;

    #pragma unroll
    for (int i = 0; i < K1_NB; i++)
        src_s[i*256 + t] = src[(size_t)(b0+i)*256 + t];

    float acc[K1_NB];
    #pragma unroll
    for (int i = 0; i < K1_NB; i++) acc[i] = 0.f;

    // q = src @ w_qs^T  (thread t owns output column c = t)
    for (int kt = 0; kt < 4; kt++) {
        __syncthreads();
        #pragma unroll
        for (int r = 0; r < 64; r++) {           // stage wt[kk][c] = w_qs[c][kt*64+kk]
            int idx = r*256 + t;
            int c = idx >> 6, kk = idx & 63;
            wt[kk*257 + c] = w_qs[c*256 + kt*64 + kk];
        }
        __syncthreads();
        float wr[64];
        #pragma unroll
        for (int kk = 0; kk < 64; kk++) wr[kk] = wt[kk*257 + t];
        #pragma unroll
        for (int i = 0; i < K1_NB; i++) {
            const float4* in4 = (const float4*)(src_s + i*256 + kt*64);
            float a = acc[i];
            #pragma unroll
            for (int k4 = 0; k4 < 16; k4++) {
                float4 v = in4[k4];
                a += wr[k4*4+0]*v.x + wr[k4*4+1]*v.y + wr[k4*4+2]*v.z + wr[k4*4+3]*v.w;
            }
            acc[i] = a;
        }
    }
    __syncthreads();
    #pragma unroll
    for (int i = 0; i < K1_NB; i++) q_s[i*256 + t] = acc[i];

    // qW[h] = q_h @ W_k,h (W_k,h = rows h*64..h*64+63 of w_ks), scaled 1/TEMP
    for (int h = 0; h < NHEAD; h++) {
        __syncthreads();
        #pragma unroll
        for (int r = 0; r < 64; r++) {           // stage wt[d][j] = w_ks[h*64+d][j]
            int idx = r*256 + t;
            int d = idx >> 8, j = idx & 255;
            wt[d*257 + j] = w_ks[(h*64 + d)*256 + j];
        }
        __syncthreads();
        float wr[64];
        #pragma unroll
        for (int d = 0; d < 64; d++) wr[d] = wt[d*257 + t];
        #pragma unroll
        for (int i = 0; i < K1_NB; i++) {
            const float4* q4 = (const float4*)(q_s + i*256 + h*64);
            float a = 0.f;
            #pragma unroll
            for (int d4 = 0; d4 < 16; d4++) {
                float4 v = q4[d4];
                a += wr[d4*4+0]*v.x + wr[d4*4+1]*v.y + wr[d4*4+2]*v.z + wr[d4*4+3]*v.w;
            }
            g_qW[(size_t)(b0+i)*1024 + h*256 + t] = a * 0.125f;
        }
    }
}

// ---------------------------------------------------------------------------
// K2: per-batch attention. seq[b] (128x256) staged in smem (stride 260 pad),
// scores (thread=row, 4 heads via qW broadcasts), masked softmax (mask row
// (4b+h) mod B, replicating reference's head-major tiling quirk), ctx to gmem.
// ---------------------------------------------------------------------------
__global__ void __launch_bounds__(256) k2_attn(const float* __restrict__ seq,
                                               const void* __restrict__ mask,
                                               int B,
                                               float* __restrict__ attn_out)
{
    float* seq_s  = s_dyn;           // 128*260
    float* qW_s   = s_dyn + 33280;   // 1024
    float* attn_s = s_dyn + 34304;   // 512
    __shared__ int s_u8;
    int t = threadIdx.x;
    int b = blockIdx.x;

    if (t == 0) s_u8 = 0;
    __syncthreads();
    {   // sniff mask dtype: bytes-of-bool vs int32 0/1 words
        unsigned wv = ((const unsigned*)mask)[t];
        if (wv > 1u) atomicOr(&s_u8, 1);
    }

    #pragma unroll
    for (int i = 0; i < 4; i++) qW_s[i*256 + t] = g_qW[(size_t)b*1024 + i*256 + t];

    const float4* sg = (const float4*)(seq + (size_t)b*32768);
    #pragma unroll
    for (int i = 0; i < 32; i++) {
        int fi = i*1024 + t*4;
        int n = fi >> 8, c = fi & 255;
        float4 v = sg[i*256 + t];
        *(float4*)(seq_s + n*260 + c) = v;
    }
    __syncthreads();
    int is_u8 = s_u8;

    if (t < 128) {
        int n = t;
        const float4* s4 = (const float4*)(seq_s + n*260);
        const float4* q0 = (const float4*)(qW_s);
        const float4* q1 = (const float4*)(qW_s + 256);
        const float4* q2 = (const float4*)(qW_s + 512);
        const float4* q3 = (const float4*)(qW_s + 768);
        float a0 = 0.f, a1 = 0.f, a2 = 0.f, a3 = 0.f;
        #pragma unroll 8
        for (int k = 0; k < 64; k++) {
            float4 v = s4[k];
            float4 w;
            w = q0[k]; a0 += v.x*w.x + v.y*w.y + v.z*w.z + v.w*w.w;
            w = q1[k]; a1 += v.x*w.x + v.y*w.y + v.z*w.z + v.w*w.w;
            w = q2[k]; a2 += v.x*w.x + v.y*w.y + v.z*w.z + v.w*w.w;
            w = q3[k]; a3 += v.x*w.x + v.y*w.y + v.z*w.z + v.w*w.w;
        }
        float sc[4] = {a0, a1, a2, a3};
        #pragma unroll
        for (int h = 0; h < NHEAD; h++) {
            int mrow = (4*b + h) % B;        // reference mask tiling quirk
            int mv;
            if (is_u8) mv = ((const unsigned char*)mask)[(size_t)mrow*128 + n];
            else       mv = ((const int*)mask)[(size_t)mrow*128 + n];
            attn_s[h*128 + n] = mv ? -1e10f : sc[h];
        }
    }
    __syncthreads();

    int w = t >> 5, lane = t & 31;
    if (w < 4) {
        float v0 = attn_s[w*128 + lane];
        float v1 = attn_s[w*128 + lane + 32];
        float v2 = attn_s[w*128 + lane + 64];
        float v3 = attn_s[w*128 + lane + 96];
        float mx = fmaxf(fmaxf(v0, v1), fmaxf(v2, v3));
        #pragma unroll
        for (int o = 16; o > 0; o >>= 1) mx = fmaxf(mx, __shfl_xor_sync(0xffffffffu, mx, o));
        float e0 = expf(v0 - mx), e1 = expf(v1 - mx), e2 = expf(v2 - mx), e3 = expf(v3 - mx);
        float s = e0 + e1 + e2 + e3;
        #pragma unroll
        for (int o = 16; o > 0; o >>= 1) s += __shfl_xor_sync(0xffffffffu, s, o);
        float inv = 1.f / s;
        e0 *= inv; e1 *= inv; e2 *= inv; e3 *= inv;
        attn_s[w*128 + lane]      = e0;
        attn_s[w*128 + lane + 32] = e1;
        attn_s[w*128 + lane + 64] = e2;
        attn_s[w*128 + lane + 96] = e3;
        if (attn_out) {
            float* ao = attn_out + (size_t)b*512 + w*128;
            ao[lane] = e0; ao[lane+32] = e1; ao[lane+64] = e2; ao[lane+96] = e3;
        }
    }
    __syncthreads();

    // ctx[h][j] = sum_n attn[h][n] * seq[n][j]   (thread t owns column j = t)
    float c0 = 0.f, c1 = 0.f, c2 = 0.f, c3 = 0.f;
    #pragma unroll 4
    for (int n = 0; n < 128; n += 4) {
        float4 p0 = *(const float4*)(attn_s + n);
        float4 p1 = *(const float4*)(attn_s + 128 + n);
        float4 p2 = *(const float4*)(attn_s + 256 + n);
        float4 p3 = *(const float4*)(attn_s + 384 + n);
        float s0 = seq_s[(n+0)*260 + t];
        float s1 = seq_s[(n+1)*260 + t];
        float s2 = seq_s[(n+2)*260 + t];
        float s3 = seq_s[(n+3)*260 + t];
        c0 += p0.x*s0 + p0.y*s1 + p0.z*s2 + p0.w*s3;
        c1 += p1.x*s0 + p1.y*s1 + p1.z*s2 + p1.w*s3;
        c2 += p2.x*s0 + p2.y*s1 + p2.z*s2 + p2.w*s3;
        c3 += p3.x*s0 + p3.y*s1 + p3.z*s2 + p3.w*s3;
    }
    float* cb = g_ctx + (size_t)b*1024;
    cb[t] = c0; cb[256 + t] = c1; cb[512 + t] = c2; cb[768 + t] = c3;
}

// ---------------------------------------------------------------------------
// K3: out-proj (W_v) -> fc (+bias +residual) -> LayerNorm -> fc1(concat)+relu
//     -> fc2 -> z.  16 batches per CTA; transposed weight tiles staged in smem;
//     64 weights cached per-thread in registers per tile.
// ---------------------------------------------------------------------------
#define K3_NB 16
__global__ void __launch_bounds__(256) k3_tail(const float* __restrict__ src,
        const float* __restrict__ w_vs,
        const float* __restrict__ fc_w,  const float* __restrict__ fc_b,
        const float* __restrict__ ln_g,  const float* __restrict__ ln_b,
        const float* __restrict__ fc1_w, const float* __restrict__ fc1_b,
        const float* __restrict__ fc2_w, const float* __restrict__ fc2_b,
        float* __restrict__ out)
{
    float* ctx_s = s_dyn;            // 16*1024
    float* src_s = s_dyn + 16384;    // 16*256
    float* o_s   = s_dyn + 20480;    // 16*256
    float* x_s   = s_dyn + 24576;    // 16*256
    float* h1_s  = s_dyn + 28672;    // 16*256
    float* wt    = s_dyn + 32768;    // 64*257
    float* mu_s  = s_dyn + 49216;    // 16
    float* rs_s  = s_dyn + 49232;    // 16
    int t  = threadIdx.x;
    int b0 = blockIdx.x * K3_NB;

    {
        const float4* g4 = (const float4*)(g_ctx + (size_t)b0*1024);
        float4* c4 = (float4*)ctx_s;
        #pragma unroll
        for (int i = 0; i < 16; i++) c4[i*256 + t] = g4[i*256 + t];
    }
    #pragma unroll
    for (int i = 0; i < K3_NB; i++) src_s[i*256 + t] = src[(size_t)(b0+i)*256 + t];

    float acc[K3_NB];

    // ---- out projection: o[i][c] = W_v[c,:] . ctx[i, c>>6, :] ----
    int hsel = t >> 6;
    #pragma unroll
    for (int i = 0; i < K3_NB; i++) acc[i] = 0.f;
    for (int kt = 0; kt < 4; kt++) {
        __syncthreads();
        #pragma unroll
        for (int r = 0; r < 64; r++) {
            int idx = r*256 + t;
            int c = idx >> 6, kk = idx & 63;
            wt[kk*257 + c] = w_vs[c*256 + kt*64 + kk];
        }
        __syncthreads();
        float wr[64];
        #pragma unroll
        for (int kk = 0; kk < 64; kk++) wr[kk] = wt[kk*257 + t];
        #pragma unroll
        for (int i = 0; i < K3_NB; i++) {
            const float4* in4 = (const float4*)(ctx_s + i*1024 + hsel*256 + kt*64);
            float a = acc[i];
            #pragma unroll
            for (int k4 = 0; k4 < 16; k4++) {
                float4 v = in4[k4];
                a += wr[k4*4+0]*v.x + wr[k4*4+1]*v.y + wr[k4*4+2]*v.z + wr[k4*4+3]*v.w;
            }
            acc[i] = a;
        }
    }
    __syncthreads();
    #pragma unroll
    for (int i = 0; i < K3_NB; i++) o_s[i*256 + t] = acc[i];

    // ---- fc: x = fc_w @ o + fc_b + src ----
    #pragma unroll
    for (int i = 0; i < K3_NB; i++) acc[i] = 0.f;
    for (int kt = 0; kt < 4; kt++) {
        __syncthreads();
        #pragma unroll
        for (int r = 0; r < 64; r++) {
            int idx = r*256 + t;
            int c = idx >> 6, kk = idx & 63;
            wt[kk*257 + c] = fc_w[c*256 + kt*64 + kk];
        }
        __syncthreads();
        float wr[64];
        #pragma unroll
        for (int kk = 0; kk < 64; kk++) wr[kk] = wt[kk*257 + t];
        #pragma unroll
        for (int i = 0; i < K3_NB; i++) {
            const float4* in4 = (const float4*)(o_s + i*256 + kt*64);
            float a = acc[i];
            #pragma unroll
            for (int k4 = 0; k4 < 16; k4++) {
                float4 v = in4[k4];
                a += wr[k4*4+0]*v.x + wr[k4*4+1]*v.y + wr[k4*4+2]*v.z + wr[k4*4+3]*v.w;
            }
            acc[i] = a;
        }
    }
    float fb = fc_b[t];
    #pragma unroll
    for (int i = 0; i < K3_NB; i++) x_s[i*256 + t] = acc[i] + fb + src_s[i*256 + t];
    __syncthreads();

    // ---- LayerNorm over 256 (warp w handles rows 2w, 2w+1) ----
    {
        int w = t >> 5, lane = t & 31;
        #pragma unroll
        for (int rr = 0; rr < 2; rr++) {
            int i = w*2 + rr;
            float s = 0.f, s2 = 0.f;
            const float4* xr = (const float4*)(x_s + i*256 + lane*8);
            #pragma unroll
            for (int q = 0; q < 2; q++) {
                float4 v = xr[q];
                s  += v.x + v.y + v.z + v.w;
                s2 += v.x*v.x + v.y*v.y + v.z*v.z + v.w*v.w;
            }
            #pragma unroll
            for (int o = 16; o > 0; o >>= 1) {
                s  += __shfl_xor_sync(0xffffffffu, s,  o);
                s2 += __shfl_xor_sync(0xffffffffu, s2, o);
            }
            if (lane == 0) {
                float mu  = s * (1.f/256.f);
                float var = s2 * (1.f/256.f) - mu*mu;
                mu_s[i] = mu;
                rs_s[i] = rsqrtf(var + 1e-5f);
            }
        }
    }
    __syncthreads();
    {
        float g = ln_g[t], be = ln_b[t];
        #pragma unroll
        for (int i = 0; i < K3_NB; i++)
            x_s[i*256 + t] = (x_s[i*256 + t] - mu_s[i]) * rs_s[i] * g + be;
    }

    // ---- fc1 on concat([x, src]) + relu ----
    #pragma unroll
    for (int i = 0; i < K3_NB; i++) acc[i] = 0.f;
    for (int kt = 0; kt < 8; kt++) {
        __syncthreads();
        #pragma unroll
        for (int r = 0; r < 64; r++) {
            int idx = r*256 + t;
            int c = idx >> 6, kk = idx & 63;
            wt[kk*257 + c] = fc1_w[c*512 + kt*64 + kk];
        }
        __syncthreads();
        float wr[64];
        #pragma unroll
        for (int kk = 0; kk < 64; kk++) wr[kk] = wt[kk*257 + t];
        const float* base = (kt < 4) ? (x_s + kt*64) : (src_s + (kt-4)*64);
        #pragma unroll
        for (int i = 0; i < K3_NB; i++) {
            const float4* in4 = (const float4*)(base + i*256);
            float a = acc[i];
            #pragma unroll
            for (int k4 = 0; k4 < 16; k4++) {
                float4 v = in4[k4];
                a += wr[k4*4+0]*v.x + wr[k4*4+1]*v.y + wr[k4*4+2]*v.z + wr[k4*4+3]*v.w;
            }
            acc[i] = a;
        }
    }
    {
        float b1 = fc1_b[t];
        __syncthreads();
        #pragma unroll
        for (int i = 0; i < K3_NB; i++) h1_s[i*256 + t] = fmaxf(acc[i] + b1, 0.f);
    }

    // ---- fc2 -> z ----
    #pragma unroll
    for (int i = 0; i < K3_NB; i++) acc[i] = 0.f;
    for (int kt = 0; kt < 4; kt++) {
        __syncthreads();
        #pragma unroll
        for (int r = 0; r < 64; r++) {
            int idx = r*256 + t;
            int c = idx >> 6, kk = idx & 63;
            wt[kk*257 + c] = fc2_w[c*256 + kt*64 + kk];
        }
        __syncthreads();
        float wr[64];
        #pragma unroll
        for (int kk = 0; kk < 64; kk++) wr[kk] = wt[kk*257 + t];
        #pragma unroll
        for (int i = 0; i < K3_NB; i++) {
            const float4* in4 = (const float4*)(h1_s + i*256 + kt*64);
            float a = acc[i];
            #pragma unroll
            for (int k4 = 0; k4 < 16; k4++) {
                float4 v = in4[k4];
                a += wr[k4*4+0]*v.x + wr[k4*4+1]*v.y + wr[k4*4+2]*v.z + wr[k4*4+3]*v.w;
            }
            acc[i] = a;
        }
    }
    {
        float b2 = fc2_b[t];
        #pragma unroll
        for (int i = 0; i < K3_NB; i++)
            out[(size_t)(b0+i)*256 + t] = acc[i] + b2;
    }
}

// ---------------------------------------------------------------------------
extern "C" void kernel_launch(void* const* d_in, const int* in_sizes, int n_in,
                              void* d_out, int out_size)
{
    const float* src   = (const float*)d_in[0];
    const float* seq   = (const float*)d_in[1];
    const void*  mask  = d_in[2];
    const float* w_qs  = (const float*)d_in[3];
    const float* w_ks  = (const float*)d_in[4];
    const float* w_vs  = (const float*)d_in[5];
    const float* fc_w  = (const float*)d_in[6];
    const float* fc_b  = (const float*)d_in[7];
    const float* ln_g  = (const float*)d_in[8];
    const float* ln_b  = (const float*)d_in[9];
    const float* fc1_w = (const float*)d_in[10];
    const float* fc1_b = (const float*)d_in[11];
    const float* fc2_w = (const float*)d_in[12];
    const float* fc2_b = (const float*)d_in[13];

    int B = in_sizes[0] / 256;
    if (B > MAXB) B = MAXB;

    float* z = (float*)d_out;
    float* attn_out = nullptr;
    // outputs: z [B,1,256] then attn [B,1,4,128] if the harness wants both
    if (out_size >= B*256 + B*512) attn_out = z + (size_t)B*256;

    size_t smem1 = (size_t)(4096 + 4096 + 64*257) * sizeof(float);
    size_t smem2 = (size_t)(128*260 + 1024 + 512) * sizeof(float);
    size_t smem3 = (size_t)(49248) * sizeof(float);
    cudaFuncSetAttribute(k1_qw,   cudaFuncAttributeMaxDynamicSharedMemorySize, (int)smem1);
    cudaFuncSetAttribute(k2_attn, cudaFuncAttributeMaxDynamicSharedMemorySize, (int)smem2);
    cudaFuncSetAttribute(k3_tail, cudaFuncAttributeMaxDynamicSharedMemorySize, (int)smem3);

    k1_qw  <<<B/K1_NB, 256, smem1>>>(src, w_qs, w_ks, B);
    k2_attn<<<B,        256, smem2>>>(seq, mask, B, attn_out);
    k3_tail<<<B/K3_NB, 256, smem3>>>(src, w_vs, fc_w, fc_b, ln_g, ln_b,
                                     fc1_w, fc1_b, fc2_w, fc2_b, z);
}

// round 2
// speedup vs baseline: 1.0456x; 1.0456x over previous
#include <cuda_runtime.h>
#include <cstdint>

#define NHEAD 4
#define DM 256
#define MAXB 2048

__device__ float g_qW[MAXB * NHEAD * DM];   // (q_h @ W_k,h)/TEMP  [b][h][j]
__device__ float g_ctx[MAXB * NHEAD * DM];  // attn @ seq          [b][h][j]

extern __shared__ float s_dyn[];

// ---------------- f32x2 / cp.async helpers ----------------
__device__ __forceinline__ uint64_t pk(float x, float y){
    uint64_t r; asm("mov.b64 %0, {%1,%2};" : "=l"(r) : "f"(x), "f"(y)); return r;
}
__device__ __forceinline__ float lo32(uint64_t v){ return __uint_as_float((unsigned)(v & 0xffffffffu)); }
__device__ __forceinline__ float hi32(uint64_t v){ return __uint_as_float((unsigned)(v >> 32)); }
__device__ __forceinline__ float hadd(uint64_t v){ return lo32(v) + hi32(v); }
__device__ __forceinline__ void fma2(uint64_t& d, uint64_t a, uint64_t b){
    asm("fma.rn.f32x2 %0, %1, %2, %0;" : "+l"(d) : "l"(a), "l"(b));
}
__device__ __forceinline__ void mul2(uint64_t& d, uint64_t r){
    asm("mul.rn.f32x2 %0, %1, %2;" : "=l"(d) : "l"(d), "l"(r));
}
__device__ __forceinline__ void ldsv2(uint64_t& a, uint64_t& b, const float* p){
    uint32_t sp = (uint32_t)__cvta_generic_to_shared(p);
    asm volatile("ld.shared.v2.u64 {%0,%1}, [%2];" : "=l"(a), "=l"(b) : "r"(sp));
}
__device__ __forceinline__ void cp16(float* dst, const float* src){
    uint32_t s = (uint32_t)__cvta_generic_to_shared(dst);
    asm volatile("cp.async.cg.shared.global [%0], [%1], 16;" :: "r"(s), "l"(src));
}
#define CP_COMMIT() asm volatile("cp.async.commit_group;" ::: "memory")
#define CP_WAIT(N)  asm volatile("cp.async.wait_group %0;" :: "n"(N) : "memory")

// ---------------------------------------------------------------------------
// Generic GEMV stage: 256 output rows (thread t -> row t of W), 16 batch rows.
// Weight half-tiles (256 rows x 32 cols, smem stride 36) cp.async double-buffered.
// acc2[i] accumulates f32x2 pairs for batch i.
// ---------------------------------------------------------------------------
#define WBUF_HALF 9216   // 256*36 floats

__device__ __forceinline__ void gemv_issue(float* wbuf, const float* wg, int wstride,
                                           int j, int t){
    float* dst = wbuf + (j & 1) * WBUF_HALF;
    const float* src = wg + j * 32;
    #pragma unroll
    for (int p = 0; p < 8; p++){
        int seg = p * 256 + t;           // 2048 16B segs
        int r = seg >> 3, pc = seg & 7;
        cp16(dst + r*36 + pc*4, src + (size_t)r * wstride + pc*4);
    }
    CP_COMMIT();
}

__device__ __forceinline__ void gemv_stage(const float* __restrict__ wg, int wstride,
                                           int kcols, float* wbuf,
                                           const float* in_base, int in_stride,
                                           uint64_t* acc2, int t){
    int NH = kcols / 32;
    gemv_issue(wbuf, wg, wstride, 0, t);
    for (int j = 0; j < NH; j++){
        if (j + 1 < NH){ gemv_issue(wbuf, wg, wstride, j+1, t); CP_WAIT(1); }
        else           { CP_WAIT(0); }
        __syncthreads();
        const float* wb = wbuf + (j & 1) * WBUF_HALF + t * 36;
        #pragma unroll
        for (int kq = 0; kq < 8; kq++){
            uint64_t w0, w1; ldsv2(w0, w1, wb + kq*4);
            #pragma unroll
            for (int i = 0; i < 16; i++){
                uint64_t a0, a1;
                ldsv2(a0, a1, in_base + i*in_stride + j*32 + kq*4);
                fma2(acc2[i], w0, a0);
                fma2(acc2[i], w1, a1);
            }
        }
        __syncthreads();
    }
}

// ---------------------------------------------------------------------------
// K1: q = src @ w_qs^T ; qW[h] = (q_h @ W_k,h) * 0.125
// ---------------------------------------------------------------------------
#define K1_NB 16
__global__ void __launch_bounds__(256) k1_qw(const float* __restrict__ src,
                                             const float* __restrict__ w_qs,
                                             const float* __restrict__ w_ks,
                                             int B)
{
    float* src_s = s_dyn;                 // 4096
    float* q_s   = s_dyn + 4096;          // 4096
    float* wbuf  = s_dyn + 8192;          // 18432
    int t  = threadIdx.x;
    int b0 = blockIdx.x * K1_NB;

    #pragma unroll
    for (int i = 0; i < K1_NB; i++)
        src_s[i*256 + t] = src[(size_t)(b0+i)*256 + t];

    uint64_t acc2[16];
    #pragma unroll
    for (int i = 0; i < 16; i++) acc2[i] = 0;

    gemv_stage(w_qs, 256, 256, wbuf, src_s, 256, acc2, t);

    #pragma unroll
    for (int i = 0; i < 16; i++) q_s[i*256 + t] = hadd(acc2[i]);
    __syncthreads();

    // head-stage: qW[i][h][t] = sum_d q[i][h*64+d] * w_ks[h*64+d][t]
    for (int h = 0; h < NHEAD; h++){
        #pragma unroll
        for (int i = 0; i < 16; i++) acc2[i] = 0;
        const float* wcol = w_ks + (size_t)h*64*256 + t;
        #pragma unroll
        for (int dc = 0; dc < 8; dc++){
            float wv[8];
            #pragma unroll
            for (int q = 0; q < 8; q++) wv[q] = __ldg(wcol + (size_t)(dc*8 + q)*256);
            uint64_t wp0 = pk(wv[0], wv[1]), wp1 = pk(wv[2], wv[3]);
            uint64_t wp2 = pk(wv[4], wv[5]), wp3 = pk(wv[6], wv[7]);
            #pragma unroll
            for (int i = 0; i < 16; i++){
                const float* qp = q_s + i*256 + h*64 + dc*8;
                uint64_t a0, a1, a2, a3;
                ldsv2(a0, a1, qp);
                ldsv2(a2, a3, qp + 4);
                fma2(acc2[i], wp0, a0); fma2(acc2[i], wp1, a1);
                fma2(acc2[i], wp2, a2); fma2(acc2[i], wp3, a3);
            }
        }
        #pragma unroll
        for (int i = 0; i < 16; i++)
            g_qW[(size_t)(b0+i)*1024 + h*256 + t] = hadd(acc2[i]) * 0.125f;
    }
}

// ---------------------------------------------------------------------------
// K2: flash-style attention. seq streamed in 4 chunks of 32 rows (cp.async,
// double buffer), warp-per-row scores + shuffle reduce, online-softmax ctx.
// ---------------------------------------------------------------------------
__device__ __forceinline__ void k2_issue(float* dst, const float* gsrc, int t){
    #pragma unroll
    for (int j = 0; j < 8; j++){
        int seg = j*256 + t;
        cp16(dst + seg*4, gsrc + seg*4);
    }
    CP_COMMIT();
}

__global__ void __launch_bounds__(256, 3) k2_attn(const float* __restrict__ seq,
                                                  const void* __restrict__ mask,
                                                  int B,
                                                  float* __restrict__ attn_out)
{
    float* chk0 = s_dyn;            // 8192
    float* chk1 = s_dyn + 8192;     // 8192
    float* qW_s = s_dyn + 16384;    // 1024
    float* sc_s = s_dyn + 17408;    // 512
    float* e_s  = s_dyn + 17920;    // 128 (layout [n][h])
    float* m_s  = s_dyn + 18048;    // 4
    float* s_s  = s_dyn + 18052;    // 4
    float* r_s  = s_dyn + 18056;    // 4 (+pad)
    __shared__ int s_u8;

    int t = threadIdx.x, b = blockIdx.x;
    int w = t >> 5, lane = t & 31;

    if (t == 0) s_u8 = 0;
    __syncthreads();
    { unsigned wv = ((const unsigned*)mask)[t]; if (wv > 1u) atomicOr(&s_u8, 1); }

    #pragma unroll
    for (int h = 0; h < 4; h++) qW_s[h*256 + t] = g_qW[(size_t)b*1024 + h*256 + t];
    if (t < 4){ m_s[t] = -1e30f; s_s[t] = 0.f; r_s[t] = 1.f; }

    const float* gseq = seq + (size_t)b*32768;
    k2_issue(chk0, gseq, t);
    k2_issue(chk1, gseq + 8192, t);

    uint64_t c01 = 0, c23 = 0;
    int is_u8 = 0;

    #pragma unroll
    for (int c = 0; c < 4; c++){
        if (c < 3) CP_WAIT(1); else CP_WAIT(0);
        __syncthreads();
        if (c == 0) is_u8 = s_u8;
        const float* cb = (c & 1) ? chk1 : chk0;

        // ---- scores: warp handles 4 rows of the 32-row chunk ----
        #pragma unroll
        for (int r = 0; r < 4; r++){
            int nl = r*8 + w;
            int ng = c*32 + nl;
            const float* vp = cb + nl*256 + lane*8;
            uint64_t v0, v1, v2, v3;
            ldsv2(v0, v1, vp);
            ldsv2(v2, v3, vp + 4);
            float sc4[4];
            #pragma unroll
            for (int h = 0; h < 4; h++){
                const float* qp = qW_s + h*256 + lane*8;
                uint64_t q0, q1, q2, q3;
                ldsv2(q0, q1, qp);
                ldsv2(q2, q3, qp + 4);
                uint64_t a = 0;
                fma2(a, v0, q0); fma2(a, v1, q1);
                fma2(a, v2, q2); fma2(a, v3, q3);
                sc4[h] = hadd(a);
            }
            #pragma unroll
            for (int o = 16; o > 0; o >>= 1){
                #pragma unroll
                for (int h = 0; h < 4; h++)
                    sc4[h] += __shfl_xor_sync(0xffffffffu, sc4[h], o);
            }
            if (lane < 4){
                int h = lane;
                int mrow = (4*b + h) % B;
                int mv = is_u8 ? (int)((const unsigned char*)mask)[(size_t)mrow*128 + ng]
                               : ((const int*)mask)[(size_t)mrow*128 + ng];
                sc_s[h*128 + ng] = mv ? -1e10f : sc4[h];
            }
        }
        __syncthreads();

        // ---- online softmax update (warps 0-3, one per head) ----
        if (w < 4){
            int h = w;
            float s = sc_s[h*128 + c*32 + lane];
            float m = s;
            #pragma unroll
            for (int o = 16; o > 0; o >>= 1) m = fmaxf(m, __shfl_xor_sync(0xffffffffu, m, o));
            float Mold = m_s[h];
            float Mnew = fmaxf(Mold, m);
            float e = expf(s - Mnew);
            float ss = e;
            #pragma unroll
            for (int o = 16; o > 0; o >>= 1) ss += __shfl_xor_sync(0xffffffffu, ss, o);
            e_s[lane*4 + h] = e;
            if (lane == 0){
                float rr = expf(Mold - Mnew);
                m_s[h] = Mnew;
                s_s[h] = s_s[h]*rr + ss;
                r_s[h] = rr;
            }
        }
        __syncthreads();

        // ---- ctx accumulate (col t, 4 heads packed in 2 f32x2 accs) ----
        {
            uint64_t r01 = *(const uint64_t*)(r_s);
            uint64_t r23 = *(const uint64_t*)(r_s + 2);
            mul2(c01, r01);
            mul2(c23, r23);
            #pragma unroll 8
            for (int n = 0; n < 32; n++){
                float sv = cb[n*256 + t];
                uint64_t svv = pk(sv, sv);
                uint64_t e01 = *(const uint64_t*)(e_s + n*4);
                uint64_t e23 = *(const uint64_t*)(e_s + n*4 + 2);
                fma2(c01, svv, e01);
                fma2(c23, svv, e23);
            }
        }
        __syncthreads();
        if (c < 2) k2_issue((c & 1) ? chk1 : chk0, gseq + (size_t)(c+2)*8192, t);
    }

    float i0 = 1.f/s_s[0], i1 = 1.f/s_s[1], i2 = 1.f/s_s[2], i3 = 1.f/s_s[3];
    float* cbg = g_ctx + (size_t)b*1024;
    cbg[t]        = lo32(c01) * i0;
    cbg[256 + t]  = hi32(c01) * i1;
    cbg[512 + t]  = lo32(c23) * i2;
    cbg[768 + t]  = hi32(c23) * i3;

    if (attn_out){
        float invs[4] = {i0, i1, i2, i3};
        #pragma unroll
        for (int k = 0; k < 2; k++){
            int idx = k*256 + t;
            int h = idx >> 7;
            attn_out[(size_t)b*512 + idx] = expf(sc_s[idx] - m_s[h]) * invs[h];
        }
    }
}

// ---------------------------------------------------------------------------
// K3: out-proj (W_v) -> fc (+bias +residual) -> LN -> fc1(concat)+relu -> fc2
// ---------------------------------------------------------------------------
#define K3_NB 16
__global__ void __launch_bounds__(256) k3_tail(const float* __restrict__ src,
        const float* __restrict__ w_vs,
        const float* __restrict__ fc_w,  const float* __restrict__ fc_b,
        const float* __restrict__ ln_g,  const float* __restrict__ ln_b,
        const float* __restrict__ fc1_w, const float* __restrict__ fc1_b,
        const float* __restrict__ fc2_w, const float* __restrict__ fc2_b,
        float* __restrict__ out)
{
    float* ctx_s = s_dyn;            // 16384
    float* src_s = s_dyn + 16384;    // 4096
    float* o_s   = s_dyn + 20480;    // 4096
    float* x_s   = s_dyn + 24576;    // 4096
    float* h1_s  = s_dyn + 28672;    // 4096
    float* wbuf  = s_dyn + 32768;    // 18432
    float* mu_s  = s_dyn + 51200;    // 16
    float* rs_s  = s_dyn + 51216;    // 16
    int t  = threadIdx.x;
    int b0 = blockIdx.x * K3_NB;

    {
        const float4* g4 = (const float4*)(g_ctx + (size_t)b0*1024);
        float4* c4 = (float4*)ctx_s;
        #pragma unroll
        for (int i = 0; i < 16; i++) c4[i*256 + t] = g4[i*256 + t];
    }
    #pragma unroll
    for (int i = 0; i < K3_NB; i++) src_s[i*256 + t] = src[(size_t)(b0+i)*256 + t];

    uint64_t acc2[16];
    int hsel = t >> 6;

    // ---- out projection ----
    #pragma unroll
    for (int i = 0; i < 16; i++) acc2[i] = 0;
    gemv_stage(w_vs, 256, 256, wbuf, ctx_s + hsel*256, 1024, acc2, t);
    #pragma unroll
    for (int i = 0; i < 16; i++) o_s[i*256 + t] = hadd(acc2[i]);

    // ---- fc + bias + residual ----
    #pragma unroll
    for (int i = 0; i < 16; i++) acc2[i] = 0;
    gemv_stage(fc_w, 256, 256, wbuf, o_s, 256, acc2, t);
    {
        float fb = fc_b[t];
        #pragma unroll
        for (int i = 0; i < 16; i++)
            x_s[i*256 + t] = hadd(acc2[i]) + fb + src_s[i*256 + t];
    }
    __syncthreads();

    // ---- LayerNorm ----
    {
        int w = t >> 5, lane = t & 31;
        #pragma unroll
        for (int rr = 0; rr < 2; rr++){
            int i = w*2 + rr;
            float s = 0.f, s2 = 0.f;
            const float4* xr = (const float4*)(x_s + i*256 + lane*8);
            #pragma unroll
            for (int q = 0; q < 2; q++){
                float4 v = xr[q];
                s  += v.x + v.y + v.z + v.w;
                s2 += v.x*v.x + v.y*v.y + v.z*v.z + v.w*v.w;
            }
            #pragma unroll
            for (int o = 16; o > 0; o >>= 1){
                s  += __shfl_xor_sync(0xffffffffu, s,  o);
                s2 += __shfl_xor_sync(0xffffffffu, s2, o);
            }
            if (lane == 0){
                float mu  = s * (1.f/256.f);
                float var = s2 * (1.f/256.f) - mu*mu;
                mu_s[i] = mu;
                rs_s[i] = rsqrtf(var + 1e-5f);
            }
        }
    }
    __syncthreads();
    {
        float g = ln_g[t], be = ln_b[t];
        #pragma unroll
        for (int i = 0; i < 16; i++)
            x_s[i*256 + t] = (x_s[i*256 + t] - mu_s[i]) * rs_s[i] * g + be;
    }

    // ---- fc1 on concat([x, src]) + relu ----
    #pragma unroll
    for (int i = 0; i < 16; i++) acc2[i] = 0;
    gemv_stage(fc1_w,       512, 256, wbuf, x_s,   256, acc2, t);
    gemv_stage(fc1_w + 256, 512, 256, wbuf, src_s, 256, acc2, t);
    {
        float b1 = fc1_b[t];
        #pragma unroll
        for (int i = 0; i < 16; i++) h1_s[i*256 + t] = fmaxf(hadd(acc2[i]) + b1, 0.f);
    }

    // ---- fc2 -> z ----
    #pragma unroll
    for (int i = 0; i < 16; i++) acc2[i] = 0;
    gemv_stage(fc2_w, 256, 256, wbuf, h1_s, 256, acc2, t);
    {
        float b2 = fc2_b[t];
        #pragma unroll
        for (int i = 0; i < 16; i++)
            out[(size_t)(b0+i)*256 + t] = hadd(acc2[i]) + b2;
    }
}

// ---------------------------------------------------------------------------
extern "C" void kernel_launch(void* const* d_in, const int* in_sizes, int n_in,
                              void* d_out, int out_size)
{
    const float* src   = (const float*)d_in[0];
    const float* seq   = (const float*)d_in[1];
    const void*  mask  = d_in[2];
    const float* w_qs  = (const float*)d_in[3];
    const float* w_ks  = (const float*)d_in[4];
    const float* w_vs  = (const float*)d_in[5];
    const float* fc_w  = (const float*)d_in[6];
    const float* fc_b  = (const float*)d_in[7];
    const float* ln_g  = (const float*)d_in[8];
    const float* ln_b  = (const float*)d_in[9];
    const float* fc1_w = (const float*)d_in[10];
    const float* fc1_b = (const float*)d_in[11];
    const float* fc2_w = (const float*)d_in[12];
    const float* fc2_b = (const float*)d_in[13];

    int B = in_sizes[0] / 256;
    if (B > MAXB) B = MAXB;

    float* z = (float*)d_out;
    float* attn_out = nullptr;
    if (out_size >= B*256 + B*512) attn_out = z + (size_t)B*256;

    size_t smem1 = (size_t)(4096 + 4096 + 18432) * sizeof(float);           // 106.5KB
    size_t smem2 = (size_t)(18064) * sizeof(float);                         // 72.3KB
    size_t smem3 = (size_t)(51232) * sizeof(float);                         // 204.9KB
    cudaFuncSetAttribute(k1_qw,   cudaFuncAttributeMaxDynamicSharedMemorySize, (int)smem1);
    cudaFuncSetAttribute(k2_attn, cudaFuncAttributeMaxDynamicSharedMemorySize, (int)smem2);
    cudaFuncSetAttribute(k3_tail, cudaFuncAttributeMaxDynamicSharedMemorySize, (int)smem3);

    k1_qw  <<<B/K1_NB, 256, smem1>>>(src, w_qs, w_ks, B);
    k2_attn<<<B,        256, smem2>>>(seq, mask, B, attn_out);
    k3_tail<<<B/K3_NB, 256, smem3>>>(src, w_vs, fc_w, fc_b, ln_g, ln_b,
                                     fc1_w, fc1_b, fc2_w, fc2_b, z);
}

// round 5
// speedup vs baseline: 1.3893x; 1.3288x over previous
#include <cuda_runtime.h>
#include <cstdint>

#define MAXB 2048

__device__ float g_qW[MAXB * 1024];   // (q_h @ W_k,h)/TEMP  [b][h][j]
__device__ float g_ctx[MAXB * 1024];  // attn @ seq          [b][h][j]

extern __shared__ float s_dyn[];

// ---------------- f32x2 / cp.async helpers ----------------
__device__ __forceinline__ uint64_t pk(float x, float y){
    uint64_t r; asm("mov.b64 %0, {%1,%2};" : "=l"(r) : "f"(x), "f"(y)); return r;
}
__device__ __forceinline__ float lo32(uint64_t v){ return __uint_as_float((unsigned)(v & 0xffffffffu)); }
__device__ __forceinline__ float hi32(uint64_t v){ return __uint_as_float((unsigned)(v >> 32)); }
__device__ __forceinline__ float hadd(uint64_t v){ return lo32(v) + hi32(v); }
__device__ __forceinline__ void fma2(uint64_t& d, uint64_t a, uint64_t b){
    asm("fma.rn.f32x2 %0, %1, %2, %0;" : "+l"(d) : "l"(a), "l"(b));
}
__device__ __forceinline__ void mul2(uint64_t& d, uint64_t r){
    asm("mul.rn.f32x2 %0, %1, %2;" : "=l"(d) : "l"(d), "l"(r));
}
__device__ __forceinline__ void ldsv2(uint64_t& a, uint64_t& b, const float* p){
    uint32_t sp = (uint32_t)__cvta_generic_to_shared(p);
    asm volatile("ld.shared.v2.u64 {%0,%1}, [%2];" : "=l"(a), "=l"(b) : "r"(sp));
}
__device__ __forceinline__ void cp16(float* dst, const float* src){
    uint32_t s = (uint32_t)__cvta_generic_to_shared(dst);
    asm volatile("cp.async.cg.shared.global [%0], [%1], 16;" :: "r"(s), "l"(src));
}
#define CP_COMMIT() asm volatile("cp.async.commit_group;" ::: "memory")
#define CP_WAIT(N)  asm volatile("cp.async.wait_group %0;" :: "n"(N) : "memory")

// ---------------------------------------------------------------------------
// Slab GEMV core: out[16 batches x 256 cols] += in[16 x K] @ W[256 x K]^T.
// Requires W row-major with CONTIGUOUS contraction: W[c][k] = wg[c*wstride+k].
// 256 threads = 64 colgroups(4 cols) x 4 batchgroups(4 batches).
// Weight slab = 32 k x 256 c (32KB), swizzled 16B units, cp.async dbl-buffer.
// ---------------------------------------------------------------------------
__device__ __forceinline__ void gemv_issue(float* wbuf, const float* __restrict__ wg,
                                           int wstride, int j, int t){
    float* dst = wbuf + (j & 1) * 8192;
    const float* src = wg + j * 32;
    #pragma unroll
    for (int p = 0; p < 8; p++){
        int u = p*256 + t;                 // 16B unit: row c = u>>3, half h = u&7
        int c = u >> 3, h = u & 7;
        int su = u ^ ((u >> 5) & 7);       // swizzle
        cp16(dst + su*4, src + (size_t)c*wstride + h*4);
    }
    CP_COMMIT();
}

__device__ __forceinline__ void gemv_slabs(const float* __restrict__ wg, int wstride,
                                           int nslab,
                                           const float* __restrict__ inp, int instride,
                                           float* wbuf, uint64_t (&acc)[4][4], int t){
    int cg = t & 63, bg = t >> 6;
    int c0 = cg * 4;
    int swm = cg & 7;
    gemv_issue(wbuf, wg, wstride, 0, t);
    if (nslab > 1) gemv_issue(wbuf, wg, wstride, 1, t);
    const float* ib0 = inp + (bg*4 + 0)*instride;
    const float* ib1 = inp + (bg*4 + 1)*instride;
    const float* ib2 = inp + (bg*4 + 2)*instride;
    const float* ib3 = inp + (bg*4 + 3)*instride;
    for (int j = 0; j < nslab; j++){
        if (j + 1 < nslab) CP_WAIT(1); else CP_WAIT(0);
        __syncthreads();
        const float* wcur = wbuf + (j & 1) * 8192;
        const float* wc0 = wcur + (c0+0)*32;
        const float* wc1 = wcur + (c0+1)*32;
        const float* wc2 = wcur + (c0+2)*32;
        const float* wc3 = wcur + (c0+3)*32;
        int kb = j * 32;
        #pragma unroll
        for (int u8 = 0; u8 < 8; u8++){
            int wof = (u8 ^ swm) * 4;
            uint64_t w[4][2];
            ldsv2(w[0][0], w[0][1], wc0 + wof);
            ldsv2(w[1][0], w[1][1], wc1 + wof);
            ldsv2(w[2][0], w[2][1], wc2 + wof);
            ldsv2(w[3][0], w[3][1], wc3 + wof);
            uint64_t iv[4][2];
            ldsv2(iv[0][0], iv[0][1], ib0 + kb + u8*4);
            ldsv2(iv[1][0], iv[1][1], ib1 + kb + u8*4);
            ldsv2(iv[2][0], iv[2][1], ib2 + kb + u8*4);
            ldsv2(iv[3][0], iv[3][1], ib3 + kb + u8*4);
            #pragma unroll
            for (int c4 = 0; c4 < 4; c4++)
                #pragma unroll
                for (int b = 0; b < 4; b++){
                    fma2(acc[c4][b], w[c4][0], iv[b][0]);
                    fma2(acc[c4][b], w[c4][1], iv[b][1]);
                }
        }
        __syncthreads();
        if (j + 2 < nslab) gemv_issue(wbuf, wg, wstride, j+2, t);
    }
}

#define ZACC(acc) { _Pragma("unroll") for (int _c=0;_c<4;_c++) _Pragma("unroll") for (int _b=0;_b<4;_b++) acc[_c][_b]=0; }

// ---------------------------------------------------------------------------
// K1: q = src @ w_qs^T ; qW[h] = (q_h @ W_k,h) * 0.125
// Head stage uses TRANSPOSED weight access (contraction stride 256):
// qW[i][h][c] = sum_d q[i][h*64+d] * w_ks[(h*64+d)*256 + c]
// ---------------------------------------------------------------------------
__global__ void __launch_bounds__(256) k1_qw(const float* __restrict__ src,
                                             const float* __restrict__ w_qs,
                                             const float* __restrict__ w_ks,
                                             int B)
{
    float* src_s = s_dyn;            // 4096
    float* q_s   = s_dyn + 4096;     // 4096
    float* wbuf  = s_dyn + 8192;     // 16384
    int t  = threadIdx.x;
    int b0 = blockIdx.x * 16;
    int cg = t & 63, bg = t >> 6;
    int c0 = cg * 4;

    #pragma unroll
    for (int p = 0; p < 4; p++){
        int u = p*256 + t;
        cp16(src_s + u*4, src + (size_t)b0*256 + u*4);
    }
    CP_COMMIT();

    uint64_t acc[4][4];
    ZACC(acc);
    gemv_slabs(w_qs, 256, 8, src_s, 256, wbuf, acc, t);
    #pragma unroll
    for (int b = 0; b < 4; b++){
        float4 v = make_float4(hadd(acc[0][b]), hadd(acc[1][b]),
                               hadd(acc[2][b]), hadd(acc[3][b]));
        *(float4*)(q_s + (bg*4+b)*256 + c0) = v;
    }
    __syncthreads();

    // ---- head stage: coalesced LDG over columns, d-pairs packed FMA2 ----
    #pragma unroll
    for (int h = 0; h < 4; h++){
        ZACC(acc);
        const float* wbase = w_ks + (size_t)(h*64)*256 + c0;
        #pragma unroll 4
        for (int d = 0; d < 64; d += 2){
            float4 wa = __ldg((const float4*)(wbase + (size_t)d*256));
            float4 wb = __ldg((const float4*)(wbase + (size_t)(d+1)*256));
            uint64_t w0 = pk(wa.x, wb.x), w1 = pk(wa.y, wb.y);
            uint64_t w2 = pk(wa.z, wb.z), w3 = pk(wa.w, wb.w);
            #pragma unroll
            for (int b = 0; b < 4; b++){
                uint64_t qp = *(const uint64_t*)(q_s + (bg*4+b)*256 + h*64 + d);
                fma2(acc[0][b], w0, qp);
                fma2(acc[1][b], w1, qp);
                fma2(acc[2][b], w2, qp);
                fma2(acc[3][b], w3, qp);
            }
        }
        #pragma unroll
        for (int b = 0; b < 4; b++){
            float4 v = make_float4(hadd(acc[0][b])*0.125f, hadd(acc[1][b])*0.125f,
                                   hadd(acc[2][b])*0.125f, hadd(acc[3][b])*0.125f);
            *(float4*)(g_qW + (size_t)(b0 + bg*4 + b)*1024 + h*256 + c0) = v;
        }
    }
}

// ---------------------------------------------------------------------------
// K2: flash-style attention, qW operand register-resident.
// ---------------------------------------------------------------------------
__device__ __forceinline__ void k2_issue(float* dst, const float* gsrc, int t){
    #pragma unroll
    for (int j = 0; j < 8; j++){
        int seg = j*256 + t;
        cp16(dst + seg*4, gsrc + seg*4);
    }
    CP_COMMIT();
}

__global__ void __launch_bounds__(256, 3) k2_attn(const float* __restrict__ seq,
                                                  const void* __restrict__ mask,
                                                  int B,
                                                  float* __restrict__ attn_out)
{
    float* chk0 = s_dyn;            // 8192
    float* chk1 = s_dyn + 8192;     // 8192
    float* sc_s = s_dyn + 16384;    // 512
    float* e_s  = s_dyn + 16896;    // 128 [n][h]
    float* m_s  = s_dyn + 17024;    // 4
    float* s_s  = s_dyn + 17028;    // 4
    float* r_s  = s_dyn + 17032;    // 4 (+pad)
    __shared__ int s_u8;

    int t = threadIdx.x, b = blockIdx.x;
    int w = t >> 5, lane = t & 31;

    if (t == 0) s_u8 = 0;
    __syncthreads();
    { unsigned wv = ((const unsigned*)mask)[t]; if (wv > 1u) atomicOr(&s_u8, 1); }

    // qW in registers: q[h][0..3] u64 = 8 floats at lane*8
    uint64_t q[4][4];
    {
        const ulonglong2* qp = (const ulonglong2*)(g_qW + (size_t)b*1024 + lane*8);
        #pragma unroll
        for (int h = 0; h < 4; h++){
            ulonglong2 v0 = qp[h*64];
            ulonglong2 v1 = qp[h*64 + 1];
            q[h][0] = v0.x; q[h][1] = v0.y; q[h][2] = v1.x; q[h][3] = v1.y;
        }
    }
    if (t < 4){ m_s[t] = -1e30f; s_s[t] = 0.f; r_s[t] = 1.f; }

    const float* gseq = seq + (size_t)b*32768;
    k2_issue(chk0, gseq, t);
    k2_issue(chk1, gseq + 8192, t);

    uint64_t c01 = 0, c23 = 0;
    int is_u8 = 0;

    #pragma unroll
    for (int c = 0; c < 4; c++){
        if (c < 3) CP_WAIT(1); else CP_WAIT(0);
        __syncthreads();
        if (c == 0) is_u8 = s_u8;
        const float* cb = (c & 1) ? chk1 : chk0;

        // ---- scores: warp handles 4 rows of the 32-row chunk ----
        #pragma unroll
        for (int r = 0; r < 4; r++){
            int nl = r*8 + w;
            int ng = c*32 + nl;
            const float* vp = cb + nl*256 + lane*8;
            uint64_t v0, v1, v2, v3;
            ldsv2(v0, v1, vp);
            ldsv2(v2, v3, vp + 4);
            float sc4[4];
            #pragma unroll
            for (int h = 0; h < 4; h++){
                uint64_t a = 0;
                fma2(a, v0, q[h][0]); fma2(a, v1, q[h][1]);
                fma2(a, v2, q[h][2]); fma2(a, v3, q[h][3]);
                sc4[h] = hadd(a);
            }
            #pragma unroll
            for (int o = 16; o > 0; o >>= 1){
                #pragma unroll
                for (int h = 0; h < 4; h++)
                    sc4[h] += __shfl_xor_sync(0xffffffffu, sc4[h], o);
            }
            if (lane < 4){
                int h = lane;
                int mrow = (4*b + h) % B;
                int mv = is_u8 ? (int)((const unsigned char*)mask)[(size_t)mrow*128 + ng]
                               : ((const int*)mask)[(size_t)mrow*128 + ng];
                sc_s[h*128 + ng] = mv ? -1e10f : sc4[h];
            }
        }
        __syncthreads();

        // ---- online softmax update (warps 0-3, one per head) ----
        if (w < 4){
            int h = w;
            float s = sc_s[h*128 + c*32 + lane];
            float m = s;
            #pragma unroll
            for (int o = 16; o > 0; o >>= 1) m = fmaxf(m, __shfl_xor_sync(0xffffffffu, m, o));
            float Mold = m_s[h];
            float Mnew = fmaxf(Mold, m);
            float e = expf(s - Mnew);
            float ss = e;
            #pragma unroll
            for (int o = 16; o > 0; o >>= 1) ss += __shfl_xor_sync(0xffffffffu, ss, o);
            e_s[lane*4 + h] = e;
            if (lane == 0){
                float rr = expf(Mold - Mnew);
                m_s[h] = Mnew;
                s_s[h] = s_s[h]*rr + ss;
                r_s[h] = rr;
            }
        }
        __syncthreads();

        // ---- ctx accumulate (col t, 4 heads in 2 f32x2 accs) ----
        {
            uint64_t r01 = *(const uint64_t*)(r_s);
            uint64_t r23 = *(const uint64_t*)(r_s + 2);
            mul2(c01, r01);
            mul2(c23, r23);
            #pragma unroll 8
            for (int n = 0; n < 32; n++){
                float sv = cb[n*256 + t];
                uint64_t svv = pk(sv, sv);
                uint64_t e01 = *(const uint64_t*)(e_s + n*4);
                uint64_t e23 = *(const uint64_t*)(e_s + n*4 + 2);
                fma2(c01, svv, e01);
                fma2(c23, svv, e23);
            }
        }
        __syncthreads();
        if (c < 2) k2_issue((c & 1) ? chk1 : chk0, gseq + (size_t)(c+2)*8192, t);
    }

    float i0 = 1.f/s_s[0], i1 = 1.f/s_s[1], i2 = 1.f/s_s[2], i3 = 1.f/s_s[3];
    float* cbg = g_ctx + (size_t)b*1024;
    cbg[t]        = lo32(c01) * i0;
    cbg[256 + t]  = hi32(c01) * i1;
    cbg[512 + t]  = lo32(c23) * i2;
    cbg[768 + t]  = hi32(c23) * i3;

    if (attn_out){
        float invs[4] = {i0, i1, i2, i3};
        #pragma unroll
        for (int k = 0; k < 2; k++){
            int idx = k*256 + t;
            int h = idx >> 7;
            attn_out[(size_t)b*512 + idx] = expf(sc_s[idx] - m_s[h]) * invs[h];
        }
    }
}

// ---------------------------------------------------------------------------
// K3: out-proj (W_v) -> fc (+bias +residual) -> LN -> fc1(concat)+relu -> fc2
// ---------------------------------------------------------------------------
__global__ void __launch_bounds__(256) k3_tail(const float* __restrict__ src,
        const float* __restrict__ w_vs,
        const float* __restrict__ fc_w,  const float* __restrict__ fc_b,
        const float* __restrict__ ln_g,  const float* __restrict__ ln_b,
        const float* __restrict__ fc1_w, const float* __restrict__ fc1_b,
        const float* __restrict__ fc2_w, const float* __restrict__ fc2_b,
        float* __restrict__ out)
{
    float* ctx_s = s_dyn;            // 16384
    float* src_s = s_dyn + 16384;    // 4096
    float* o_s   = s_dyn + 20480;    // 4096
    float* x_s   = s_dyn + 24576;    // 4096
    float* h1_s  = s_dyn + 28672;    // 4096
    float* wbuf  = s_dyn + 32768;    // 16384
    float* mu_s  = s_dyn + 49152;    // 16
    float* rs_s  = s_dyn + 49168;    // 16
    int t  = threadIdx.x;
    int b0 = blockIdx.x * 16;
    int cg = t & 63, bg = t >> 6;
    int c0 = cg * 4;

    #pragma unroll
    for (int p = 0; p < 16; p++){
        int u = p*256 + t;
        cp16(ctx_s + u*4, g_ctx + (size_t)b0*1024 + u*4);
    }
    #pragma unroll
    for (int p = 0; p < 4; p++){
        int u = p*256 + t;
        cp16(src_s + u*4, src + (size_t)b0*256 + u*4);
    }
    CP_COMMIT();

    uint64_t acc[4][4];

    // ---- out projection: col c uses ctx head c>>6 ----
    ZACC(acc);
    gemv_slabs(w_vs, 256, 8, ctx_s + (cg >> 4)*256, 1024, wbuf, acc, t);
    #pragma unroll
    for (int b = 0; b < 4; b++){
        float4 v = make_float4(hadd(acc[0][b]), hadd(acc[1][b]),
                               hadd(acc[2][b]), hadd(acc[3][b]));
        *(float4*)(o_s + (bg*4+b)*256 + c0) = v;
    }

    // ---- fc + bias + residual ----
    ZACC(acc);
    gemv_slabs(fc_w, 256, 8, o_s, 256, wbuf, acc, t);
    {
        float4 fb = *(const float4*)(fc_b + c0);
        #pragma unroll
        for (int b = 0; b < 4; b++){
            int i = bg*4 + b;
            float4 sv = *(const float4*)(src_s + i*256 + c0);
            float4 v = make_float4(hadd(acc[0][b]) + fb.x + sv.x,
                                   hadd(acc[1][b]) + fb.y + sv.y,
                                   hadd(acc[2][b]) + fb.z + sv.z,
                                   hadd(acc[3][b]) + fb.w + sv.w);
            *(float4*)(x_s + i*256 + c0) = v;
        }
    }
    __syncthreads();

    // ---- LayerNorm (warp w handles rows 2w, 2w+1) ----
    {
        int w = t >> 5, lane = t & 31;
        #pragma unroll
        for (int rr = 0; rr < 2; rr++){
            int i = w*2 + rr;
            float s = 0.f, s2 = 0.f;
            const float4* xr = (const float4*)(x_s + i*256 + lane*8);
            #pragma unroll
            for (int qq = 0; qq < 2; qq++){
                float4 v = xr[qq];
                s  += v.x + v.y + v.z + v.w;
                s2 += v.x*v.x + v.y*v.y + v.z*v.z + v.w*v.w;
            }
            #pragma unroll
            for (int o = 16; o > 0; o >>= 1){
                s  += __shfl_xor_sync(0xffffffffu, s,  o);
                s2 += __shfl_xor_sync(0xffffffffu, s2, o);
            }
            if (lane == 0){
                float mu  = s * (1.f/256.f);
                float var = s2 * (1.f/256.f) - mu*mu;
                mu_s[i] = mu;
                rs_s[i] = rsqrtf(var + 1e-5f);
            }
        }
    }
    __syncthreads();
    {
        float g = ln_g[t], be = ln_b[t];
        #pragma unroll
        for (int i = 0; i < 16; i++)
            x_s[i*256 + t] = (x_s[i*256 + t] - mu_s[i]) * rs_s[i] * g + be;
    }
    __syncthreads();

    // ---- fc1 on concat([x, src]) + relu ----
    ZACC(acc);
    gemv_slabs(fc1_w,       512, 8, x_s,   256, wbuf, acc, t);
    gemv_slabs(fc1_w + 256, 512, 8, src_s, 256, wbuf, acc, t);
    {
        float4 b1 = *(const float4*)(fc1_b + c0);
        #pragma unroll
        for (int b = 0; b < 4; b++){
            float4 v = make_float4(fmaxf(hadd(acc[0][b]) + b1.x, 0.f),
                                   fmaxf(hadd(acc[1][b]) + b1.y, 0.f),
                                   fmaxf(hadd(acc[2][b]) + b1.z, 0.f),
                                   fmaxf(hadd(acc[3][b]) + b1.w, 0.f));
            *(float4*)(h1_s + (bg*4+b)*256 + c0) = v;
        }
    }
    __syncthreads();

    // ---- fc2 -> z ----
    ZACC(acc);
    gemv_slabs(fc2_w, 256, 8, h1_s, 256, wbuf, acc, t);
    {
        float4 b2 = *(const float4*)(fc2_b + c0);
        #pragma unroll
        for (int b = 0; b < 4; b++){
            float4 v = make_float4(hadd(acc[0][b]) + b2.x,
                                   hadd(acc[1][b]) + b2.y,
                                   hadd(acc[2][b]) + b2.z,
                                   hadd(acc[3][b]) + b2.w);
            *(float4*)(out + (size_t)(b0 + bg*4 + b)*256 + c0) = v;
        }
    }
}

// ---------------------------------------------------------------------------
extern "C" void kernel_launch(void* const* d_in, const int* in_sizes, int n_in,
                              void* d_out, int out_size)
{
    const float* src   = (const float*)d_in[0];
    const float* seq   = (const float*)d_in[1];
    const void*  mask  = d_in[2];
    const float* w_qs  = (const float*)d_in[3];
    const float* w_ks  = (const float*)d_in[4];
    const float* w_vs  = (const float*)d_in[5];
    const float* fc_w  = (const float*)d_in[6];
    const float* fc_b  = (const float*)d_in[7];
    const float* ln_g  = (const float*)d_in[8];
    const float* ln_b  = (const float*)d_in[9];
    const float* fc1_w = (const float*)d_in[10];
    const float* fc1_b = (const float*)d_in[11];
    const float* fc2_w = (const float*)d_in[12];
    const float* fc2_b = (const float*)d_in[13];

    int B = in_sizes[0] / 256;
    if (B > MAXB) B = MAXB;

    float* z = (float*)d_out;
    float* attn_out = nullptr;
    if (out_size >= B*256 + B*512) attn_out = z + (size_t)B*256;

    size_t smem1 = (size_t)(4096 + 4096 + 16384) * sizeof(float);   // 96KB
    size_t smem2 = (size_t)(17040) * sizeof(float);                 // ~66.6KB
    size_t smem3 = (size_t)(49184) * sizeof(float);                 // ~192.1KB
    cudaFuncSetAttribute(k1_qw,   cudaFuncAttributeMaxDynamicSharedMemorySize, (int)smem1);
    cudaFuncSetAttribute(k2_attn, cudaFuncAttributeMaxDynamicSharedMemorySize, (int)smem2);
    cudaFuncSetAttribute(k3_tail, cudaFuncAttributeMaxDynamicSharedMemorySize, (int)smem3);

    k1_qw  <<<B/16, 256, smem1>>>(src, w_qs, w_ks, B);
    k2_attn<<<B,    256, smem2>>>(seq, mask, B, attn_out);
    k3_tail<<<B/16, 256, smem3>>>(src, w_vs, fc_w, fc_b, ln_g, ln_b,
                                  fc1_w, fc1_b, fc2_w, fc2_b, z);
}